// round 3
// baseline (speedup 1.0000x reference)
#include <cuda_runtime.h>
#include <cuda_bf16.h>
#include <math.h>

// Problem constants
#define B_   4096
#define OBS_ 512
#define T_   10
#define E_   8
#define W_   1024
#define H_   12
#define XCOL (OBS_ + T_)   // 522
#define EPS_ 1e-8f

// GEMM tiling
#define BM 128
#define BN 128
#define BK 16
#define TM 8
#define TN 8
// 256 threads per block, 16x16 thread grid, each computes 8x8

// Scratch: two (E, B, W) fp32 buffers, 134 MB each (static device allocation,
// per harness rules no cudaMalloc allowed).
__device__ float g_buf0[(size_t)E_ * B_ * W_];
__device__ float g_buf1[(size_t)E_ * B_ * W_];

// ---------------------------------------------------------------------------
// Batched SGEMM: C[e] = act(A[e] (MxK, ld=lda) @ Bm[e] (KxN) + bias[e])
// grid = (N/BN, M/BM, E)
// ---------------------------------------------------------------------------
__global__ void __launch_bounds__(256) gemm_bias_act_kernel(
    const float* __restrict__ A, int lda, long long aStride,
    const float* __restrict__ Bm,     // + e*K*N
    const float* __restrict__ bias,   // + e*N
    float* __restrict__ C,            // + e*M*N
    int M, int N, int K, int doRelu)
{
    const int e = blockIdx.z;
    A    += (long long)e * aStride;
    Bm   += (long long)e * K * N;
    bias += (long long)e * N;
    C    += (long long)e * M * N;

    __shared__ float As[BK][BM];
    __shared__ float Bs[BK][BN];

    const int tid = threadIdx.x;
    const int tx  = tid & 15;          // 0..15 -> N direction
    const int ty  = tid >> 4;          // 0..15 -> M direction
    const int m0  = blockIdx.y * BM;
    const int n0  = blockIdx.x * BN;

    float acc[TM][TN];
    #pragma unroll
    for (int i = 0; i < TM; i++)
        #pragma unroll
        for (int j = 0; j < TN; j++)
            acc[i][j] = 0.f;

    for (int k0 = 0; k0 < K; k0 += BK) {
        // --- load A tile (BM x BK), transposed into As[k][m]
        // 512 quads of 4 k-consecutive floats; 2 quads per thread
        #pragma unroll
        for (int i = 0; i < 2; i++) {
            int q  = tid + i * 256;     // 0..511
            int m  = q >> 2;            // 0..127
            int kq = (q & 3) * 4;       // 0,4,8,12
            const float* ap = A + (long long)(m0 + m) * lda + (k0 + kq);
            float a0 = ap[0], a1 = ap[1], a2 = ap[2], a3 = ap[3];
            As[kq + 0][m] = a0;
            As[kq + 1][m] = a1;
            As[kq + 2][m] = a2;
            As[kq + 3][m] = a3;
        }
        // --- load B tile (BK x BN) via float4, coalesced
        #pragma unroll
        for (int i = 0; i < 2; i++) {
            int q  = tid + i * 256;     // 0..511
            int k  = q >> 5;            // 0..15
            int n4 = (q & 31) * 4;      // 0..124 step 4
            const float4 v = *reinterpret_cast<const float4*>(
                Bm + (long long)(k0 + k) * N + (n0 + n4));
            *reinterpret_cast<float4*>(&Bs[k][n4]) = v;
        }
        __syncthreads();

        #pragma unroll
        for (int k = 0; k < BK; k++) {
            float ra[TM], rb[TN];
            #pragma unroll
            for (int i = 0; i < TM; i++) ra[i] = As[k][ty * TM + i];
            #pragma unroll
            for (int j = 0; j < TN; j++) rb[j] = Bs[k][tx * TN + j];
            #pragma unroll
            for (int i = 0; i < TM; i++)
                #pragma unroll
                for (int j = 0; j < TN; j++)
                    acc[i][j] = fmaf(ra[i], rb[j], acc[i][j]);
        }
        __syncthreads();
    }

    // epilogue: bias (+ReLU), float4 stores (each thread owns 8 consecutive n)
    const int nbase = n0 + tx * TN;
    float4 bv0 = *reinterpret_cast<const float4*>(bias + nbase);
    float4 bv1 = *reinterpret_cast<const float4*>(bias + nbase + 4);
    #pragma unroll
    for (int i = 0; i < TM; i++) {
        const int m = m0 + ty * TM + i;
        float4 o0, o1;
        o0.x = acc[i][0] + bv0.x; o0.y = acc[i][1] + bv0.y;
        o0.z = acc[i][2] + bv0.z; o0.w = acc[i][3] + bv0.w;
        o1.x = acc[i][4] + bv1.x; o1.y = acc[i][5] + bv1.y;
        o1.z = acc[i][6] + bv1.z; o1.w = acc[i][7] + bv1.w;
        if (doRelu) {
            o0.x = fmaxf(o0.x, 0.f); o0.y = fmaxf(o0.y, 0.f);
            o0.z = fmaxf(o0.z, 0.f); o0.w = fmaxf(o0.w, 0.f);
            o1.x = fmaxf(o1.x, 0.f); o1.y = fmaxf(o1.y, 0.f);
            o1.z = fmaxf(o1.z, 0.f); o1.w = fmaxf(o1.w, 0.f);
        }
        float* cp = C + (long long)m * N + nbase;
        *reinterpret_cast<float4*>(cp)     = o0;
        *reinterpret_cast<float4*>(cp + 4) = o1;
    }
}

// ---------------------------------------------------------------------------
// Fused epilogue: classical Gram-Schmidt over E vectors (dim W), te-weighted
// combine, tanh, task-selected head GEMV. One block (256 thr) per batch row.
// ---------------------------------------------------------------------------
__global__ void __launch_bounds__(256) gs_head_kernel(
    const float* __restrict__ eo,     // (E, B, W)
    const float* __restrict__ x,      // (B, 522) - last 10 cols one-hot
    const float* __restrict__ teW,    // (T, E)
    const float* __restrict__ headW,  // (T, W, H)
    const float* __restrict__ headB,  // (T, H)
    float* __restrict__ out)          // (B, H)
{
    const int b   = blockIdx.x;
    const int tid = threadIdx.x;

    __shared__ float basis[E_][W_];    // 32 KB
    __shared__ float s_red[9];
    __shared__ float s_coef[E_];
    __shared__ float s_te[E_];
    __shared__ int   s_task;
    __shared__ float s_hred[H_][8];

    // task id = argmax over one-hot tail of x
    if (tid == 0) {
        int task = 0;
        float best = x[(long long)b * XCOL + OBS_];
        #pragma unroll
        for (int t = 1; t < T_; t++) {
            float v = x[(long long)b * XCOL + OBS_ + t];
            if (v > best) { best = v; task = t; }
        }
        s_task = task;
    }
    __syncthreads();
    if (tid < E_) s_te[tid] = teW[s_task * E_ + tid];
    __syncthreads();

    const int lane = tid & 31;
    const int warp = tid >> 5;

    float feat[4] = {0.f, 0.f, 0.f, 0.f};

    for (int i = 0; i < E_; i++) {
        // load v_i (4 elems per thread, coalesced)
        float v[4];
        #pragma unroll
        for (int j = 0; j < 4; j++)
            v[j] = eo[((long long)i * B_ + b) * W_ + tid + j * 256];

        // dot(v_i, basis_p) for p < i  (classical GS: against ORIGINAL v)
        for (int p = 0; p < i; p++) {
            float d = 0.f;
            #pragma unroll
            for (int j = 0; j < 4; j++)
                d += v[j] * basis[p][tid + j * 256];
            #pragma unroll
            for (int o = 16; o > 0; o >>= 1)
                d += __shfl_down_sync(0xffffffffu, d, o);
            if (lane == 0) s_red[warp] = d;
            __syncthreads();
            if (tid == 0) {
                float s = 0.f;
                #pragma unroll
                for (int w2 = 0; w2 < 8; w2++) s += s_red[w2];
                s_coef[p] = s;
            }
            __syncthreads();
        }

        // w = v - sum_p coef_p * basis_p ; norm
        float w[4];
        float nsq = 0.f;
        #pragma unroll
        for (int j = 0; j < 4; j++) {
            float s = v[j];
            for (int p = 0; p < i; p++)
                s -= s_coef[p] * basis[p][tid + j * 256];
            w[j] = s;
            nsq += s * s;
        }
        #pragma unroll
        for (int o = 16; o > 0; o >>= 1)
            nsq += __shfl_down_sync(0xffffffffu, nsq, o);
        if (lane == 0) s_red[warp] = nsq;
        __syncthreads();
        if (tid == 0) {
            float s = 0.f;
            #pragma unroll
            for (int w2 = 0; w2 < 8; w2++) s += s_red[w2];
            s_red[8] = s;
        }
        __syncthreads();
        const float inv = 1.f / (sqrtf(s_red[8]) + EPS_);
        const float te_i = s_te[i];
        #pragma unroll
        for (int j = 0; j < 4; j++) {
            const float bb = w[j] * inv;
            basis[i][tid + j * 256] = bb;
            feat[j] += te_i * bb;
        }
        __syncthreads();   // basis[i] visible for next iteration; s_red reusable
    }

    // head: out[b][h] = sum_k tanh(feat_k) * headW[task][k][h] + headB[task][h]
    const int task = s_task;
    float acc[H_];
    #pragma unroll
    for (int h = 0; h < H_; h++) acc[h] = 0.f;
    #pragma unroll
    for (int j = 0; j < 4; j++) {
        const int k = tid + j * 256;
        const float f = tanhf(feat[j]);
        const float* hw = headW + ((long long)task * W_ + k) * H_;
        #pragma unroll
        for (int h = 0; h < H_; h++)
            acc[h] = fmaf(f, hw[h], acc[h]);
    }
    #pragma unroll
    for (int h = 0; h < H_; h++) {
        float a = acc[h];
        #pragma unroll
        for (int o = 16; o > 0; o >>= 1)
            a += __shfl_down_sync(0xffffffffu, a, o);
        if (lane == 0) s_hred[h][warp] = a;
    }
    __syncthreads();
    if (tid < H_) {
        float s = 0.f;
        #pragma unroll
        for (int w2 = 0; w2 < 8; w2++) s += s_hred[tid][w2];
        out[(long long)b * H_ + tid] = s + headB[task * H_ + tid];
    }
}

// ---------------------------------------------------------------------------
extern "C" void kernel_launch(void* const* d_in, const int* in_sizes, int n_in,
                              void* d_out, int out_size)
{
    const float* x      = (const float*)d_in[0];
    const float* te_W   = (const float*)d_in[1];
    const float* W0     = (const float*)d_in[2];
    const float* b0     = (const float*)d_in[3];
    const float* W1     = (const float*)d_in[4];
    const float* b1     = (const float*)d_in[5];
    const float* W2     = (const float*)d_in[6];
    const float* b2     = (const float*)d_in[7];
    const float* head_W = (const float*)d_in[8];
    const float* head_b = (const float*)d_in[9];
    float* out = (float*)d_out;

    float *h0, *h1;
    cudaGetSymbolAddress((void**)&h0, g_buf0);
    cudaGetSymbolAddress((void**)&h1, g_buf1);

    dim3 grid(W_ / BN, B_ / BM, E_);   // (8, 32, 8)

    // h0 = relu(obs @ W0 + b0)   A = x (ld 522, batch-shared), K = 512
    gemm_bias_act_kernel<<<grid, 256>>>(x, XCOL, 0LL, W0, b0, h0,
                                        B_, W_, OBS_, 1);
    // h1 = relu(h0 @ W1 + b1)    K = 1024
    gemm_bias_act_kernel<<<grid, 256>>>(h0, W_, (long long)B_ * W_, W1, b1, h1,
                                        B_, W_, W_, 1);
    // eo = h1 @ W2 + b2 (no relu), reuse h0
    gemm_bias_act_kernel<<<grid, 256>>>(h1, W_, (long long)B_ * W_, W2, b2, h0,
                                        B_, W_, W_, 0);
    // Gram-Schmidt + te combine + tanh + head
    gs_head_kernel<<<B_, 256>>>(h0, x, te_W, head_W, head_b, out);
}

// round 17
// speedup vs baseline: 2.0468x; 2.0468x over previous
#include <cuda_runtime.h>
#include <cuda_bf16.h>
#include <math.h>
#include <stdint.h>

// ---------------------------------------------------------------------------
// Problem constants
#define B_   4096
#define OBS_ 512
#define T_   10
#define E_   8
#define W_   1024
#define H_   12
#define XCOL (OBS_ + T_)   // 522
#define EPS_ 1e-8f

// ---------------------------------------------------------------------------
// Static device scratch (no cudaMalloc allowed), 1024B aligned for cp.async 16B.
__device__ __align__(1024) __nv_bfloat16 g_xh[(size_t)B_ * OBS_];
__device__ __align__(1024) __nv_bfloat16 g_xl[(size_t)B_ * OBS_];
__device__ __align__(1024) __nv_bfloat16 g_w0h[(size_t)E_ * W_ * OBS_];   // (E, N=1024, K=512)
__device__ __align__(1024) __nv_bfloat16 g_w0l[(size_t)E_ * W_ * OBS_];
__device__ __align__(1024) __nv_bfloat16 g_w1h[(size_t)E_ * W_ * W_];     // (E, 1024, 1024)
__device__ __align__(1024) __nv_bfloat16 g_w1l[(size_t)E_ * W_ * W_];
__device__ __align__(1024) __nv_bfloat16 g_w2h[(size_t)E_ * W_ * W_];
__device__ __align__(1024) __nv_bfloat16 g_w2l[(size_t)E_ * W_ * W_];
__device__ __align__(1024) __nv_bfloat16 g_h0h[(size_t)E_ * B_ * W_];
__device__ __align__(1024) __nv_bfloat16 g_h0l[(size_t)E_ * B_ * W_];
__device__ __align__(1024) __nv_bfloat16 g_h1h[(size_t)E_ * B_ * W_];
__device__ __align__(1024) __nv_bfloat16 g_h1l[(size_t)E_ * B_ * W_];
__device__ __align__(1024) float         g_eo [(size_t)E_ * B_ * W_];

// ---------------------------------------------------------------------------
__device__ __forceinline__ uint32_t smem_u32(const void* p) {
    uint32_t a;
    asm("{ .reg .u64 t; cvta.to.shared.u64 t, %1; cvt.u32.u64 %0, t; }" : "=r"(a) : "l"(p));
    return a;
}
__device__ __forceinline__ void cp16(uint32_t s, const void* g) {
    asm volatile("cp.async.cg.shared.global [%0], [%1], 16;" :: "r"(s), "l"(g));
}
#define LDSM_X4(r0, r1, r2, r3, addr) \
    asm volatile("ldmatrix.sync.aligned.m8n8.x4.shared.b16 {%0,%1,%2,%3}, [%4];" \
                 : "=r"(r0), "=r"(r1), "=r"(r2), "=r"(r3) : "r"(addr))
#define MMA_BF16(c, a, b) \
    asm volatile("mma.sync.aligned.m16n8k16.row.col.f32.bf16.bf16.f32 " \
                 "{%0,%1,%2,%3}, {%4,%5,%6,%7}, {%8,%9}, {%0,%1,%2,%3};" \
                 : "+f"((c)[0]), "+f"((c)[1]), "+f"((c)[2]), "+f"((c)[3]) \
                 : "r"((a)[0]), "r"((a)[1]), "r"((a)[2]), "r"((a)[3]), \
                   "r"((b)[0]), "r"((b)[1]))

// GEMM tiling: CTA 128x128, BK=32, 8 warps (2 m x 4 n), warp tile 64x32.
#define BK      32
#define ROWB    80                     // 32 bf16 = 64B + 16B pad, conflict-free ldmatrix
#define TILE_B  (128 * ROWB)           // 10240 B
#define STAGE_B (4 * TILE_B)           // Ah,Al,Bh,Bl = 40960 B
#define SB_OFF  (2 * STAGE_B)          // bias floats after 2 stages
#define GEMM_SMEM (SB_OFF + 128 * 4)   // 82432 B

// Load one stage: Ah,Al rows [0,128) x k[k0,k0+32), Bh,Bl same from (N,K) weights.
__device__ __forceinline__ void load_stage(
    uint32_t sstage,
    const __nv_bfloat16* gAh, const __nv_bfloat16* gAl,
    const __nv_bfloat16* gBh, const __nv_bfloat16* gBl,
    int k0, int K, int tid)
{
    #pragma unroll
    for (int j = 0; j < 2; j++) {
        const int c   = tid * 2 + j;        // 0..511
        const int row = c >> 2;             // 0..127
        const int kc  = c & 3;              // 16B chunk
        const uint32_t so = (uint32_t)(row * ROWB + kc * 16);
        const long long go = (long long)row * K + k0 + kc * 8;
        cp16(sstage + so,              gAh + go);
        cp16(sstage + TILE_B + so,     gAl + go);
        cp16(sstage + 2*TILE_B + so,   gBh + go);
        cp16(sstage + 3*TILE_B + so,   gBl + go);
    }
    asm volatile("cp.async.commit_group;");
}

// ---------------------------------------------------------------------------
// bf16-split batched GEMM via warp-level mma.sync (baseline ISA, works on sm_103).
// D[e] = A[e](MxK) @ Wt[e]^T + bias ; Wt stored (E,N,K).
// MODE 0: relu + bf16 hi/lo split out.  MODE 1: fp32 out.
// grid = (N/128, M/128, E), block = 256
template<int MODE>
__global__ void __launch_bounds__(256) gemm_mma(
    const __nv_bfloat16* __restrict__ Ah, const __nv_bfloat16* __restrict__ Al,
    long long aStride, int K,
    const __nv_bfloat16* __restrict__ Bth, const __nv_bfloat16* __restrict__ Btl,
    const float* __restrict__ bias,
    __nv_bfloat16* __restrict__ Ch, __nv_bfloat16* __restrict__ Cl,
    float* __restrict__ Cf)
{
    extern __shared__ char smem[];
    const int e    = blockIdx.z;
    const int m0   = blockIdx.y * 128;
    const int n0   = blockIdx.x * 128;
    const int tid  = threadIdx.x;
    const int wid  = tid >> 5, lane = tid & 31;
    const int wm   = wid >> 2;          // 0..1 -> m offset wm*64
    const int wn   = wid & 3;           // 0..3 -> n offset wn*32
    const uint32_t sbase = smem_u32(smem);

    const __nv_bfloat16* gAh = Ah + (long long)e * aStride + (long long)m0 * K;
    const __nv_bfloat16* gAl = Al + (long long)e * aStride + (long long)m0 * K;
    const __nv_bfloat16* gBh = Bth + ((long long)e * W_ + n0) * K;
    const __nv_bfloat16* gBl = Btl + ((long long)e * W_ + n0) * K;

    // bias tile -> smem
    float* sb = (float*)(smem + SB_OFF);
    if (tid < 128) sb[tid] = bias[(long long)e * W_ + n0 + tid];

    float acc[4][4][4];
    #pragma unroll
    for (int mi = 0; mi < 4; mi++)
        #pragma unroll
        for (int ni = 0; ni < 4; ni++)
            #pragma unroll
            for (int c = 0; c < 4; c++)
                acc[mi][ni][c] = 0.f;

    // ldmatrix per-lane address components
    const int arow = lane & 15, akb = (lane >> 4) * 8;            // A: m16 x k16
    const int bnr  = (lane & 7) + ((lane >> 4) << 3);             // B: 16 n-rows
    const int bkb  = ((lane >> 3) & 1) * 8;

    const int niter = K / BK;
    load_stage(sbase, gAh, gAl, gBh, gBl, 0, K, tid);

    for (int i = 0; i < niter; i++) {
        if (i + 1 < niter) {
            load_stage(sbase + ((i + 1) & 1) * STAGE_B,
                       gAh, gAl, gBh, gBl, (i + 1) * BK, K, tid);
            asm volatile("cp.async.wait_group 1;");
        } else {
            asm volatile("cp.async.wait_group 0;");
        }
        __syncthreads();

        const uint32_t st  = sbase + (i & 1) * STAGE_B;
        const uint32_t sAh = st, sAl = st + TILE_B;
        const uint32_t sBh = st + 2*TILE_B, sBl = st + 3*TILE_B;

        #pragma unroll
        for (int kc = 0; kc < BK; kc += 16) {
            uint32_t ah[4][4], al[4][4], bh[4][2], bl[4][2];
            #pragma unroll
            for (int mi = 0; mi < 4; mi++) {
                const uint32_t ao = (uint32_t)((wm*64 + mi*16 + arow) * ROWB + (kc + akb) * 2);
                LDSM_X4(ah[mi][0], ah[mi][1], ah[mi][2], ah[mi][3], sAh + ao);
                LDSM_X4(al[mi][0], al[mi][1], al[mi][2], al[mi][3], sAl + ao);
            }
            #pragma unroll
            for (int pi = 0; pi < 2; pi++) {
                const uint32_t bo = (uint32_t)((wn*32 + pi*16 + bnr) * ROWB + (kc + bkb) * 2);
                uint32_t r0, r1, r2, r3;
                LDSM_X4(r0, r1, r2, r3, sBh + bo);
                bh[2*pi][0] = r0; bh[2*pi][1] = r1; bh[2*pi+1][0] = r2; bh[2*pi+1][1] = r3;
                LDSM_X4(r0, r1, r2, r3, sBl + bo);
                bl[2*pi][0] = r0; bl[2*pi][1] = r1; bl[2*pi+1][0] = r2; bl[2*pi+1][1] = r3;
            }
            #pragma unroll
            for (int mi = 0; mi < 4; mi++)
                #pragma unroll
                for (int ni = 0; ni < 4; ni++) {
                    MMA_BF16(acc[mi][ni], ah[mi], bh[ni]);
                    MMA_BF16(acc[mi][ni], ah[mi], bl[ni]);
                    MMA_BF16(acc[mi][ni], al[mi], bh[ni]);
                }
        }
        __syncthreads();
    }

    // epilogue: atom (mi,ni): c0,c1 -> (row = mi*16 + lane/4, cols 2*(lane%4)+0,1)
    //           c2,c3 -> row+8.  Global row = m0 + wm*64 + ..., col = n0 + wn*32 + ni*8 + ...
    const int r0l = (lane >> 2);
    const int c0l = (lane & 3) * 2;
    #pragma unroll
    for (int mi = 0; mi < 4; mi++) {
        #pragma unroll
        for (int ni = 0; ni < 4; ni++) {
            #pragma unroll
            for (int half = 0; half < 2; half++) {
                const int m   = m0 + wm*64 + mi*16 + r0l + half*8;
                const int cl  = wn*32 + ni*8 + c0l;
                float v0 = acc[mi][ni][half*2]     + sb[cl];
                float v1 = acc[mi][ni][half*2 + 1] + sb[cl + 1];
                const long long o = ((long long)e * B_ + m) * W_ + n0 + cl;
                if (MODE == 0) {
                    v0 = fmaxf(v0, 0.f); v1 = fmaxf(v1, 0.f);
                    __nv_bfloat16 h0 = __float2bfloat16(v0);
                    __nv_bfloat16 h1 = __float2bfloat16(v1);
                    __nv_bfloat16 l0 = __float2bfloat16(v0 - __bfloat162float(h0));
                    __nv_bfloat16 l1 = __float2bfloat16(v1 - __bfloat162float(h1));
                    __nv_bfloat162 ph; ph.x = h0; ph.y = h1;
                    __nv_bfloat162 pl; pl.x = l0; pl.y = l1;
                    *reinterpret_cast<__nv_bfloat162*>(Ch + o) = ph;
                    *reinterpret_cast<__nv_bfloat162*>(Cl + o) = pl;
                } else {
                    float2 fo; fo.x = v0; fo.y = v1;
                    *reinterpret_cast<float2*>(Cf + o) = fo;
                }
            }
        }
    }
}

// ---------------------------------------------------------------------------
// Prep: split x obs columns into bf16 hi/lo (B,512)
__global__ void split_x_kernel(const float* __restrict__ x,
                               __nv_bfloat16* __restrict__ xh,
                               __nv_bfloat16* __restrict__ xl)
{
    int idx = blockIdx.x * 256 + threadIdx.x;
    if (idx >= B_ * OBS_) return;
    int row = idx >> 9, col = idx & 511;
    float v = x[(long long)row * XCOL + col];
    __nv_bfloat16 h = __float2bfloat16(v);
    xh[idx] = h;
    xl[idx] = __float2bfloat16(v - __bfloat162float(h));
}

// Prep: W (E,K,N) fp32 -> transposed (E,N,K) bf16 hi/lo
__global__ void transpose_split_kernel(const float* __restrict__ Wm,
                                       __nv_bfloat16* __restrict__ Th,
                                       __nv_bfloat16* __restrict__ Tl,
                                       int K, int N)
{
    __shared__ float t[32][33];
    const int e  = blockIdx.z;
    const int kb = blockIdx.y * 32, nb = blockIdx.x * 32;
    const int tx = threadIdx.x, ty = threadIdx.y;   // (32, 8)
    const float* src = Wm + (long long)e * K * N;
    #pragma unroll
    for (int j = 0; j < 32; j += 8)
        t[ty + j][tx] = src[(long long)(kb + ty + j) * N + nb + tx];
    __syncthreads();
    __nv_bfloat16* dh = Th + (long long)e * N * K;
    __nv_bfloat16* dl = Tl + (long long)e * N * K;
    #pragma unroll
    for (int j = 0; j < 32; j += 8) {
        float v = t[tx][ty + j];
        __nv_bfloat16 h = __float2bfloat16(v);
        long long o = (long long)(nb + ty + j) * K + kb + tx;
        dh[o] = h;
        dl[o] = __float2bfloat16(v - __bfloat162float(h));
    }
}

// ---------------------------------------------------------------------------
// Fused Gram-Schmidt + te combine + tanh + task head (unchanged from R3 pass)
__global__ void __launch_bounds__(256) gs_head_kernel(
    const float* __restrict__ eo, const float* __restrict__ x,
    const float* __restrict__ teW, const float* __restrict__ headW,
    const float* __restrict__ headB, float* __restrict__ out)
{
    const int b   = blockIdx.x;
    const int tid = threadIdx.x;
    __shared__ float basis[E_][W_];
    __shared__ float s_red[9];
    __shared__ float s_coef[E_];
    __shared__ float s_te[E_];
    __shared__ int   s_task;
    __shared__ float s_hred[H_][8];

    if (tid == 0) {
        int task = 0;
        float best = x[(long long)b * XCOL + OBS_];
        #pragma unroll
        for (int t = 1; t < T_; t++) {
            float v = x[(long long)b * XCOL + OBS_ + t];
            if (v > best) { best = v; task = t; }
        }
        s_task = task;
    }
    __syncthreads();
    if (tid < E_) s_te[tid] = teW[s_task * E_ + tid];
    __syncthreads();

    const int lane = tid & 31, warp = tid >> 5;
    float feat[4] = {0.f, 0.f, 0.f, 0.f};

    for (int i = 0; i < E_; i++) {
        float v[4];
        #pragma unroll
        for (int j = 0; j < 4; j++)
            v[j] = eo[((long long)i * B_ + b) * W_ + tid + j * 256];

        for (int p = 0; p < i; p++) {
            float d = 0.f;
            #pragma unroll
            for (int j = 0; j < 4; j++)
                d += v[j] * basis[p][tid + j * 256];
            #pragma unroll
            for (int o = 16; o > 0; o >>= 1)
                d += __shfl_down_sync(0xffffffffu, d, o);
            if (lane == 0) s_red[warp] = d;
            __syncthreads();
            if (tid == 0) {
                float s = 0.f;
                #pragma unroll
                for (int w2 = 0; w2 < 8; w2++) s += s_red[w2];
                s_coef[p] = s;
            }
            __syncthreads();
        }

        float w[4];
        float nsq = 0.f;
        #pragma unroll
        for (int j = 0; j < 4; j++) {
            float s = v[j];
            for (int p = 0; p < i; p++)
                s -= s_coef[p] * basis[p][tid + j * 256];
            w[j] = s;
            nsq += s * s;
        }
        #pragma unroll
        for (int o = 16; o > 0; o >>= 1)
            nsq += __shfl_down_sync(0xffffffffu, nsq, o);
        if (lane == 0) s_red[warp] = nsq;
        __syncthreads();
        if (tid == 0) {
            float s = 0.f;
            #pragma unroll
            for (int w2 = 0; w2 < 8; w2++) s += s_red[w2];
            s_red[8] = s;
        }
        __syncthreads();
        const float inv = 1.f / (sqrtf(s_red[8]) + EPS_);
        const float te_i = s_te[i];
        #pragma unroll
        for (int j = 0; j < 4; j++) {
            const float bb = w[j] * inv;
            basis[i][tid + j * 256] = bb;
            feat[j] += te_i * bb;
        }
        __syncthreads();
    }

    const int task = s_task;
    float acc[H_];
    #pragma unroll
    for (int h = 0; h < H_; h++) acc[h] = 0.f;
    #pragma unroll
    for (int j = 0; j < 4; j++) {
        const int k = tid + j * 256;
        const float f = tanhf(feat[j]);
        const float* hw = headW + ((long long)task * W_ + k) * H_;
        #pragma unroll
        for (int h = 0; h < H_; h++)
            acc[h] = fmaf(f, hw[h], acc[h]);
    }
    #pragma unroll
    for (int h = 0; h < H_; h++) {
        float a = acc[h];
        #pragma unroll
        for (int o = 16; o > 0; o >>= 1)
            a += __shfl_down_sync(0xffffffffu, a, o);
        if (lane == 0) s_hred[h][warp] = a;
    }
    __syncthreads();
    if (tid < H_) {
        float s = 0.f;
        #pragma unroll
        for (int w2 = 0; w2 < 8; w2++) s += s_hred[tid][w2];
        out[(long long)b * H_ + tid] = s + headB[task * H_ + tid];
    }
}

// ---------------------------------------------------------------------------
extern "C" void kernel_launch(void* const* d_in, const int* in_sizes, int n_in,
                              void* d_out, int out_size)
{
    const float* x      = (const float*)d_in[0];
    const float* te_W   = (const float*)d_in[1];
    const float* W0     = (const float*)d_in[2];
    const float* b0     = (const float*)d_in[3];
    const float* W1     = (const float*)d_in[4];
    const float* b1     = (const float*)d_in[5];
    const float* W2     = (const float*)d_in[6];
    const float* b2     = (const float*)d_in[7];
    const float* head_W = (const float*)d_in[8];
    const float* head_b = (const float*)d_in[9];
    float* out = (float*)d_out;

    __nv_bfloat16 *xh, *xl, *w0h, *w0l, *w1h, *w1l, *w2h, *w2l;
    __nv_bfloat16 *h0h, *h0l, *h1h, *h1l;
    float *eo;
    cudaGetSymbolAddress((void**)&xh,  g_xh);
    cudaGetSymbolAddress((void**)&xl,  g_xl);
    cudaGetSymbolAddress((void**)&w0h, g_w0h);
    cudaGetSymbolAddress((void**)&w0l, g_w0l);
    cudaGetSymbolAddress((void**)&w1h, g_w1h);
    cudaGetSymbolAddress((void**)&w1l, g_w1l);
    cudaGetSymbolAddress((void**)&w2h, g_w2h);
    cudaGetSymbolAddress((void**)&w2l, g_w2l);
    cudaGetSymbolAddress((void**)&h0h, g_h0h);
    cudaGetSymbolAddress((void**)&h0l, g_h0l);
    cudaGetSymbolAddress((void**)&h1h, g_h1h);
    cudaGetSymbolAddress((void**)&h1l, g_h1l);
    cudaGetSymbolAddress((void**)&eo,  g_eo);

    cudaFuncSetAttribute(gemm_mma<0>, cudaFuncAttributeMaxDynamicSharedMemorySize, GEMM_SMEM);
    cudaFuncSetAttribute(gemm_mma<1>, cudaFuncAttributeMaxDynamicSharedMemorySize, GEMM_SMEM);

    // prep: split/transpose
    split_x_kernel<<<(B_ * OBS_ + 255) / 256, 256>>>(x, xh, xl);
    transpose_split_kernel<<<dim3(W_ / 32, OBS_ / 32, E_), dim3(32, 8)>>>(W0, w0h, w0l, OBS_, W_);
    transpose_split_kernel<<<dim3(W_ / 32, W_ / 32, E_),  dim3(32, 8)>>>(W1, w1h, w1l, W_, W_);
    transpose_split_kernel<<<dim3(W_ / 32, W_ / 32, E_),  dim3(32, 8)>>>(W2, w2h, w2l, W_, W_);

    dim3 ggrid(W_ / 128, B_ / 128, E_);   // (8, 32, 8)

    // layer 0: h0 = relu(x @ W0 + b0), K=512, A shared across experts
    gemm_mma<0><<<ggrid, 256, GEMM_SMEM>>>(xh, xl, 0LL, OBS_,
                                           w0h, w0l, b0, h0h, h0l, nullptr);
    // layer 1: h1 = relu(h0 @ W1 + b1), K=1024
    gemm_mma<0><<<ggrid, 256, GEMM_SMEM>>>(h0h, h0l, (long long)B_ * W_, W_,
                                           w1h, w1l, b1, h1h, h1l, nullptr);
    // layer 2: eo = h1 @ W2 + b2 (fp32 out, no relu)
    gemm_mma<1><<<ggrid, 256, GEMM_SMEM>>>(h1h, h1l, (long long)B_ * W_, W_,
                                           w2h, w2l, b2, nullptr, nullptr, eo);

    gs_head_kernel<<<B_, 256>>>(eo, x, te_W, head_W, head_b, out);
}